// round 17
// baseline (speedup 1.0000x reference)
#include <cuda_runtime.h>
#include <math.h>

#define NB 16
#define NC 3
#define HH 512
#define WW 512
#define PLANE (HH*WW)
#define NPL (NB*NC)            // 48 planes
#define NELEM (NPL*PLANE)      // 12,582,912 per tensor

__device__ float g_blur0[NELEM];
__device__ float g_blur1[NELEM];
__device__ double g_acc[2];

// 9-tap Gaussian, sigma=1, truncate=4 (matches scipy, normalized)
__constant__ float KG[9] = {
    1.3383062e-04f, 4.4318615e-03f, 5.3991128e-02f, 2.4197145e-01f,
    3.9894346e-01f, 2.4197145e-01f, 5.3991128e-02f, 4.4318615e-03f,
    1.3383062e-04f
};

// Effective 3x3 channel-mixing matrix (9-tap over n=3, symmetric padding)
__constant__ float WC[3][3] = {
    {0.64091491f, 0.29609641f, 0.06298868f},
    {0.29609641f, 0.40780718f, 0.29609641f},
    {0.06298868f, 0.29609641f, 0.64091491f}
};

__device__ __forceinline__ int refl512(int i) {
    if (i < 0)    return -1 - i;
    if (i >= 512) return 1023 - i;
    return i;
}
__device__ __forceinline__ int refl16(int i) {
    if (i < 0)   return -1 - i;
    if (i > 15)  return 31 - i;
    return i;
}

// Fused log + W-blur + H-blur. 64x32 output tile. Grid (8,16,96), block 256.
__global__ __launch_bounds__(256) void blur_hw_kernel(const float* __restrict__ Ie,
                                                      const float* __restrict__ Ig)
{
    __shared__ float lv[40][80];   // log tile, cols = global [x0-8, x0+72)
    __shared__ float wb[40][64];   // after W-blur

    const int t = threadIdx.x;
    if (blockIdx.x == 0 && blockIdx.y == 0 && blockIdx.z == 0 && t == 0) {
        g_acc[0] = 0.0; g_acc[1] = 0.0;
    }

    const int z  = blockIdx.z;
    const int zz = (z < NPL) ? z : (z - NPL);
    const float* src = ((z < NPL) ? Ie : Ig) + (size_t)zz * PLANE;
    float*       dst = ((z < NPL) ? g_blur0 : g_blur1) + (size_t)zz * PLANE;

    const int x0 = blockIdx.x * 64;
    const int y0 = blockIdx.y * 32;
    const bool xedge = (blockIdx.x == 0) || (blockIdx.x == 7);

    // Stage 1: 40 rows x 20 float4 = 800 vector loads, log applied
    #pragma unroll
    for (int idx = t; idx < 800; idx += 256) {
        const int row = idx / 20, c4 = idx % 20;
        const int gy = refl512(y0 - 4 + row);
        const float* srow = src + gy * WW;
        const int gx = x0 - 8 + c4 * 4;
        float4 v;
        if (!xedge) {
            v = *(const float4*)(srow + gx);
        } else {
            v.x = srow[refl512(gx    )];
            v.y = srow[refl512(gx + 1)];
            v.z = srow[refl512(gx + 2)];
            v.w = srow[refl512(gx + 3)];
        }
        v.x = __logf(v.x + 1e-6f);
        v.y = __logf(v.y + 1e-6f);
        v.z = __logf(v.z + 1e-6f);
        v.w = __logf(v.w + 1e-6f);
        *(float4*)&lv[row][c4 * 4] = v;
    }
    __syncthreads();

    // Stage 2: W-blur, 4 outputs/thread from a 12-wide register window
    #pragma unroll
    for (int idx = t; idx < 640; idx += 256) {
        const int row = idx >> 4, c = (idx & 15) * 4;
        const float4 a = *(const float4*)&lv[row][c + 4];
        const float4 b = *(const float4*)&lv[row][c + 8];
        const float4 d = *(const float4*)&lv[row][c + 12];
        const float win[12] = {a.x,a.y,a.z,a.w, b.x,b.y,b.z,b.w, d.x,d.y,d.z,d.w};
        float4 o;
        float o0 = 0.f, o1 = 0.f, o2 = 0.f, o3 = 0.f;
        #pragma unroll
        for (int j = 0; j < 9; j++) {
            const float kg = KG[j];
            o0 += kg * win[j];
            o1 += kg * win[j + 1];
            o2 += kg * win[j + 2];
            o3 += kg * win[j + 3];
        }
        o.x = o0; o.y = o1; o.z = o2; o.w = o3;
        *(float4*)&wb[row][c] = o;
    }
    __syncthreads();

    // Stage 3: H-blur, 8 outputs/thread from a 16-tall register window
    {
        const int x  = t & 63;
        const int yb = (t >> 6) * 8;            // 0,8,16,24
        float w[16];
        #pragma unroll
        for (int r = 0; r < 16; r++) w[r] = wb[yb + r][x];
        #pragma unroll
        for (int k = 0; k < 8; k++) {
            float s = 0.f;
            #pragma unroll
            for (int j = 0; j < 9; j++) s += KG[j] * w[k + j];
            dst[(y0 + yb + k) * WW + x0 + x] = s;
        }
    }
}

// Loss kernel: 512 threads = 64 pixels x 8 subs; each sub owns 2 batches
// (6 planes). pix-major mapping -> conflict-free stride-64 smem.
__global__ __launch_bounds__(512) void loss_kernel(const float* __restrict__ Ie,
                                                   const float* __restrict__ Ig)
{
    __shared__ float sa[NPL][64];
    __shared__ float sb[NPL][64];
    __shared__ double ssr[16], ssl[16];

    const int t    = threadIdx.x;
    const int off0 = blockIdx.x * 64;
    const int pix  = t & 63;
    const int sub  = t >> 6;   // 0..7, owns batches 2*sub, 2*sub+1

    // Stage blurred logs (vectorized, coalesced)
    #pragma unroll
    for (int idx = t; idx < NPL * 16; idx += 512) {
        const int pl = idx >> 4, q = (idx & 15) * 4;
        const size_t g = (size_t)pl * PLANE + off0 + q;
        *(float4*)&sa[pl][q] = *(const float4*)(g_blur0 + g);
        *(float4*)&sb[pl][q] = *(const float4*)(g_blur1 + g);
    }

    // Preload raw inputs into registers (overlaps with staging latency)
    float rawE[6], rawG[6];
    #pragma unroll
    for (int m = 0; m < 6; m++) {
        const size_t g = (size_t)(6 * sub + m) * PLANE + off0 + pix;
        rawE[m] = Ie[g];
        rawG[m] = Ig[g];
    }
    __syncthreads();

    // Channel blur (3x3 matrix) in place, rows 6*sub .. 6*sub+5
    #pragma unroll
    for (int k = 0; k < 2; k++) {
        const int r = (2 * sub + k) * 3;
        const float a0 = sa[r][pix], a1 = sa[r+1][pix], a2 = sa[r+2][pix];
        sa[r  ][pix] = WC[0][0]*a0 + WC[0][1]*a1 + WC[0][2]*a2;
        sa[r+1][pix] = WC[1][0]*a0 + WC[1][1]*a1 + WC[1][2]*a2;
        sa[r+2][pix] = WC[2][0]*a0 + WC[2][1]*a1 + WC[2][2]*a2;
        const float b0 = sb[r][pix], b1 = sb[r+1][pix], b2 = sb[r+2][pix];
        sb[r  ][pix] = WC[0][0]*b0 + WC[0][1]*b1 + WC[0][2]*b2;
        sb[r+1][pix] = WC[1][0]*b0 + WC[1][1]*b1 + WC[1][2]*b2;
        sb[r+2][pix] = WC[2][0]*b0 + WC[2][1]*b1 + WC[2][2]*b2;
    }
    __syncthreads();

    // Batch blur: 10-wide sliding window per channel, 2 outputs each
    float s0[6], s1[6];
    #pragma unroll
    for (int c = 0; c < 3; c++) {
        float w[10], x[10];
        #pragma unroll
        for (int tt = 0; tt < 10; tt++) {
            const int mm = refl16(2 * sub - 4 + tt);
            w[tt] = sa[mm * 3 + c][pix];
            x[tt] = sb[mm * 3 + c][pix];
        }
        #pragma unroll
        for (int k = 0; k < 2; k++) {
            float a0 = 0.f, a1 = 0.f;
            #pragma unroll
            for (int j = 0; j < 9; j++) {
                a0 += KG[j] * w[k + j];
                a1 += KG[j] * x[k + j];
            }
            s0[k * 3 + c] = a0;
            s1[k * 3 + c] = a1;
        }
    }

    // Loss: exp(log(I+eps)-s) == (I+eps)*exp(-s), exp(L)=exp(s)
    double sr = 0.0, sl = 0.0;
    #pragma unroll
    for (int m = 0; m < 6; m++) {
        const float se = s0[m], sg = s1[m];
        const float le = __expf(se);
        const float lg = __expf(sg);
        const float re = (rawE[m] + 1e-6f) * __expf(-se);
        const float rg = (rawG[m] + 1e-6f) * __expf(-sg);
        const float dr = re - rg;
        const float dl = le - lg;
        sr += (double)(dr * dr);
        sl += (double)(dl * dl);
    }

    // Block reduce
    #pragma unroll
    for (int o = 16; o; o >>= 1) {
        sr += __shfl_down_sync(0xffffffffu, sr, o);
        sl += __shfl_down_sync(0xffffffffu, sl, o);
    }
    const int lane = t & 31, wid = t >> 5;
    if (lane == 0) { ssr[wid] = sr; ssl[wid] = sl; }
    __syncthreads();
    if (t == 0) {
        double a = 0.0, b = 0.0;
        #pragma unroll
        for (int i = 0; i < 16; i++) { a += ssr[i]; b += ssl[i]; }
        atomicAdd(&g_acc[0], a);
        atomicAdd(&g_acc[1], b);
    }
}

__global__ void finalize_kernel(float* __restrict__ out)
{
    out[0] = (float)((g_acc[0] + g_acc[1]) * (1.0 / (double)NELEM));
}

extern "C" void kernel_launch(void* const* d_in, const int* in_sizes, int n_in,
                              void* d_out, int out_size)
{
    const float* Ie = (const float*)d_in[0];
    const float* Ig = (const float*)d_in[1];
    float* out = (float*)d_out;

    dim3 b1(256), g1(8, 16, 2 * NPL);
    blur_hw_kernel<<<g1, b1>>>(Ie, Ig);

    loss_kernel<<<PLANE / 64, 512>>>(Ie, Ig);

    finalize_kernel<<<1, 1>>>(out);
}